// round 7
// baseline (speedup 1.0000x reference)
#include <cuda_runtime.h>
#include <cuda_fp16.h>
#include <math.h>

// Problem constants
#define Jc 166
#define Rc 864
#define Oc 8
#define Bc 128
#define BT 8            // batches per CTA (one per warp, warps 0-7)
#define TT 288          // threads per CTA (864/3), 9 warps
#define KR 3            // routes per thread in gen
#define RW 27           // routes per lane in routing (864/32)

#define W_ELEMS (Jc * Rc * Oc * 4)   // 4,589,568
#define U_ELEMS (Bc * Rc * 4)        //   442,368
#define NROUTES (Jc * Rc)            //   143,424

#define SMEM_BYTES (BT * Rc * 16)    // u_hat fp16-packed uint4: 110592 B

typedef unsigned long long ull;

// fp16 copies of the inputs (static device buffers: no allocation)
// W16g layout: per route (j*Rc+r), 4 uint4; uint4 q holds half2 pairs
//   (W[2q][i], W[2q+1][i]) for i = 0..3 in .x,.y,.z,.w
__device__ uint4  W16g[NROUTES * 4];   // 9.18 MB
__device__ __half u16g[U_ELEMS];       // 0.88 MB

// ---------------- scalar fp16 helpers ----------------
__device__ __forceinline__ unsigned int pk2(float a, float b) {
    __half2 h = __floats2half2_rn(a, b);
    return *reinterpret_cast<unsigned int*>(&h);
}
__device__ __forceinline__ float2 up2(unsigned int v) {
    __half2 h = *reinterpret_cast<__half2*>(&v);
    return __half22float2(h);
}
__device__ __forceinline__ unsigned int hadd2u(unsigned int a, unsigned int b) {
    __half2 r = __hadd2(*reinterpret_cast<__half2*>(&a), *reinterpret_cast<__half2*>(&b));
    return *reinterpret_cast<unsigned int*>(&r);
}

// ---------------- packed f32x2 helpers (sm_103a) ----------------
__device__ __forceinline__ ull up2x(unsigned int v) {   // half2 -> f32x2
    ull r;
    asm("{\n\t.reg .f16 h0, h1;\n\t.reg .f32 lo, hi;\n\t"
        "mov.b32 {h0, h1}, %1;\n\t"
        "cvt.f32.f16 lo, h0;\n\t"
        "cvt.f32.f16 hi, h1;\n\t"
        "mov.b64 %0, {lo, hi};\n\t}"
        : "=l"(r) : "r"(v));
    return r;
}
__device__ __forceinline__ ull packf2(float lo, float hi) {
    ull r;
    asm("mov.b64 %0, {%1, %2};" : "=l"(r) : "f"(lo), "f"(hi));
    return r;
}
__device__ __forceinline__ void unpackf2(ull v, float& lo, float& hi) {
    asm("mov.b64 {%0, %1}, %2;" : "=f"(lo), "=f"(hi) : "l"(v));
}
__device__ __forceinline__ ull ffma2(ull a, ull b, ull c) {
    ull d;
    asm("fma.rn.f32x2 %0, %1, %2, %3;" : "=l"(d) : "l"(a), "l"(b), "l"(c));
    return d;
}
__device__ __forceinline__ ull fmul2(ull a, ull b) {
    ull d;
    asm("mul.rn.f32x2 %0, %1, %2;" : "=l"(d) : "l"(a), "l"(b));
    return d;
}

// butterfly-reduce N floats across the warp (all lanes get result)
template<int N>
__device__ __forceinline__ void wredN(float* p) {
#pragma unroll
    for (int s = 16; s; s >>= 1)
#pragma unroll
        for (int q = 0; q < N; q++)
            p[q] += __shfl_xor_sync(0xffffffffu, p[q], s);
}

// ------------------- prep: fp32 -> fp16 (W reordered, u flat) -------------------
__global__ void __launch_bounds__(256)
prep_kernel(const float* __restrict__ W, const float* __restrict__ u)
{
    const int idx = blockIdx.x * blockDim.x + threadIdx.x;
    if (idx < NROUTES) {
        const float4* f4 = (const float4*)(W + (size_t)idx * 32);
#pragma unroll
        for (int q = 0; q < 4; q++) {
            const float4 lo = f4[2 * q];       // o = 2q,   i = 0..3
            const float4 hi = f4[2 * q + 1];   // o = 2q+1, i = 0..3
            uint4 o;
            o.x = pk2(lo.x, hi.x);
            o.y = pk2(lo.y, hi.y);
            o.z = pk2(lo.z, hi.z);
            o.w = pk2(lo.w, hi.w);
            W16g[(size_t)idx * 4 + q] = o;
        }
    }
    if (idx < U_ELEMS / 8) {
        const float4* p = (const float4*)u + (size_t)idx * 2;
        const float4 a = p[0], b = p[1];
        uint4 o;
        o.x = pk2(a.x, a.y); o.y = pk2(a.z, a.w);
        o.z = pk2(b.x, b.y); o.w = pk2(b.z, b.w);
        ((uint4*)u16g)[idx] = o;
    }
}

// ------------------------------ main kernel ------------------------------
__global__ void __launch_bounds__(TT, 2)
digitcaps_kernel(float* __restrict__ out)
{
    extern __shared__ uint4 uh[];              // [BT][Rc]

    const int g    = blockIdx.x;
    const int j    = blockIdx.y;
    const int b0   = g * BT;
    const int t    = threadIdx.x;
    const int warp = t >> 5;
    const int lane = t & 31;

    const uint4* __restrict__ W4  = W16g + (size_t)j * Rc * 4;
    const uint2* __restrict__ u2p = (const uint2*)u16g;

    // ====== gen: u_hat -> smem (fp16 packed), f32x2 math, all 9 warps =========
#pragma unroll
    for (int k = 0; k < KR; k++) {
        const int r = t + k * TT;
        // wp[q][i] = f32x2 (W[2q][i], W[2q+1][i])
        ull wp[4][4];
#pragma unroll
        for (int q = 0; q < 4; q++) {
            const uint4 wq = W4[(size_t)r * 4 + q];
            wp[q][0] = up2x(wq.x);
            wp[q][1] = up2x(wq.y);
            wp[q][2] = up2x(wq.z);
            wp[q][3] = up2x(wq.w);
        }
#pragma unroll
        for (int b = 0; b < BT; b++) {
            const uint2 uu = u2p[(size_t)(b0 + b) * Rc + r];
            const float2 u01 = up2(uu.x), u23 = up2(uu.y);
            const ull ub0 = packf2(u01.x, u01.x);
            const ull ub1 = packf2(u01.y, u01.y);
            const ull ub2 = packf2(u23.x, u23.x);
            const ull ub3 = packf2(u23.y, u23.y);
            uint4 pkv;
            unsigned int* pk = (unsigned int*)&pkv;
#pragma unroll
            for (int q = 0; q < 4; q++) {
                ull acc = fmul2(wp[q][0], ub0);
                acc = ffma2(wp[q][1], ub1, acc);
                acc = ffma2(wp[q][2], ub2, acc);
                acc = ffma2(wp[q][3], ub3, acc);
                float lo, hi; unpackf2(acc, lo, hi);
                pk[q] = pk2(lo, hi);
            }
            uh[b * Rc + r] = pkv;
        }
    }
    __syncthreads();        // the only barrier

    // ============== routing: warp b owns batch b, fully warp-private ===========
    if (warp < BT) {
        const uint4* __restrict__ base = uh + warp * Rc + lane;

        // ---- pass 0 (half2): s0 = mean_r u_hat ; v0 = squash(s0) ----
        // fp16 accumulation here only perturbs softmax weights (harmless).
        unsigned int h0 = 0u, h1 = 0u, h2 = 0u, h3 = 0u;
#pragma unroll 9
        for (int i = 0; i < RW; i++) {
            const uint4 v = base[i * 32];
            h0 = hadd2u(h0, v.x); h1 = hadd2u(h1, v.y);
            h2 = hadd2u(h2, v.z); h3 = hadd2u(h3, v.w);
        }
#pragma unroll
        for (int s = 16; s; s >>= 1) {
            h0 = hadd2u(h0, __shfl_xor_sync(0xffffffffu, h0, s));
            h1 = hadd2u(h1, __shfl_xor_sync(0xffffffffu, h1, s));
            h2 = hadd2u(h2, __shfl_xor_sync(0xffffffffu, h2, s));
            h3 = hadd2u(h3, __shfl_xor_sync(0xffffffffu, h3, s));
        }
        float v0[Oc];
        {
            const float2 f0 = up2(h0), f1 = up2(h1), f2 = up2(h2), f3 = up2(h3);
            float s[Oc] = { f0.x, f0.y, f1.x, f1.y, f2.x, f2.y, f3.x, f3.y };
            float sq = 0.f;
#pragma unroll
            for (int o = 0; o < Oc; o++) { s[o] *= (1.0f / (float)Rc); sq += s[o] * s[o]; }
            const float scl = sqrtf(sq) / (1.f + sq);
#pragma unroll
            for (int o = 0; o < Oc; o++) v0[o] = s[o] * scl;
        }

        // ---- pass 1: e = exp(<uh,v0>) ; weighted sums (f32x2) -> v1 ----
        float p[9];
        {
            const ull vp0 = packf2(v0[0], v0[1]), vp1 = packf2(v0[2], v0[3]);
            const ull vp2 = packf2(v0[4], v0[5]), vp3 = packf2(v0[6], v0[7]);
            ull P0 = 0ull, P1 = 0ull, P2 = 0ull, P3 = 0ull;
            float p8 = 0.f;
#pragma unroll 9
            for (int i = 0; i < RW; i++) {
                const uint4 v = base[i * 32];
                const ull q0 = up2x(v.x), q1 = up2x(v.y), q2 = up2x(v.z), q3 = up2x(v.w);
                ull da = fmul2(q0, vp0);
                da = ffma2(q1, vp1, da);
                da = ffma2(q2, vp2, da);
                da = ffma2(q3, vp3, da);
                float al, ah; unpackf2(da, al, ah);
                const float e = __expf(al + ah);
                const ull e2 = packf2(e, e);
                P0 = ffma2(q0, e2, P0); P1 = ffma2(q1, e2, P1);
                P2 = ffma2(q2, e2, P2); P3 = ffma2(q3, e2, P3);
                p8 += e;
            }
            unpackf2(P0, p[0], p[1]); unpackf2(P1, p[2], p[3]);
            unpackf2(P2, p[4], p[5]); unpackf2(P3, p[6], p[7]);
            p[8] = p8;
        }
        wredN<9>(p);
        float vs[Oc];   // vs = v0 + v1  (b2 = <uh,v0> + <uh,v1> = <uh,vs>)
        {
            const float inv = 1.f / p[8];
            float sq = 0.f;
#pragma unroll
            for (int o = 0; o < Oc; o++) { p[o] *= inv; sq += p[o] * p[o]; }
            const float scl = sqrtf(sq) / (1.f + sq);
#pragma unroll
            for (int o = 0; o < Oc; o++) vs[o] = v0[o] + p[o] * scl;
        }

        // ---- pass 2: e = exp(<uh,vs>) ; weighted sums (f32x2) -> v2 -> out ----
        {
            const ull vp0 = packf2(vs[0], vs[1]), vp1 = packf2(vs[2], vs[3]);
            const ull vp2 = packf2(vs[4], vs[5]), vp3 = packf2(vs[6], vs[7]);
            ull P0 = 0ull, P1 = 0ull, P2 = 0ull, P3 = 0ull;
            float p8 = 0.f;
#pragma unroll 9
            for (int i = 0; i < RW; i++) {
                const uint4 v = base[i * 32];
                const ull q0 = up2x(v.x), q1 = up2x(v.y), q2 = up2x(v.z), q3 = up2x(v.w);
                ull da = fmul2(q0, vp0);
                da = ffma2(q1, vp1, da);
                da = ffma2(q2, vp2, da);
                da = ffma2(q3, vp3, da);
                float al, ah; unpackf2(da, al, ah);
                const float e = __expf(al + ah);
                const ull e2 = packf2(e, e);
                P0 = ffma2(q0, e2, P0); P1 = ffma2(q1, e2, P1);
                P2 = ffma2(q2, e2, P2); P3 = ffma2(q3, e2, P3);
                p8 += e;
            }
            unpackf2(P0, p[0], p[1]); unpackf2(P1, p[2], p[3]);
            unpackf2(P2, p[4], p[5]); unpackf2(P3, p[6], p[7]);
            p[8] = p8;
        }
        wredN<9>(p);
        {
            const float inv = 1.f / p[8];
            float sq = 0.f;
#pragma unroll
            for (int o = 0; o < Oc; o++) { p[o] *= inv; sq += p[o] * p[o]; }
            const float scl = sqrtf(sq) / (1.f + sq);
            if (lane < Oc)
                out[((size_t)(b0 + warp) * Jc + j) * Oc + lane] = p[lane] * scl;
        }
    }
}

extern "C" void kernel_launch(void* const* d_in, const int* in_sizes, int n_in,
                              void* d_out, int out_size)
{
    const float* u = (const float*)d_in[0];
    const float* W = (const float*)d_in[1];
    if (n_in >= 2 && in_sizes[0] > in_sizes[1]) {   // defensive order check
        const float* tmp = u; u = W; W = tmp;
    }

    cudaFuncSetAttribute(digitcaps_kernel,
                         cudaFuncAttributeMaxDynamicSharedMemorySize, SMEM_BYTES);

    // 1) convert W (o-pair-interleaved) and u to fp16 staging buffers
    prep_kernel<<<(NROUTES + 255) / 256, 256>>>(W, u);
    // 2) fused capsule-routing kernel
    dim3 grid(Bc / BT, Jc);   // (16, 166)
    digitcaps_kernel<<<grid, TT, SMEM_BYTES>>>((float*)d_out);
}

// round 8
// speedup vs baseline: 1.0351x; 1.0351x over previous
#include <cuda_runtime.h>
#include <cuda_fp16.h>
#include <math.h>

// Problem constants
#define Jc 166
#define Rc 864
#define Oc 8
#define Bc 128
#define BT 8            // batches per CTA (one per warp, warps 0-7)
#define TT 288          // threads per CTA (864/3), 9 warps
#define KR 3            // routes per thread in gen
#define RW 27           // routes per lane in routing (864/32)

#define W_ELEMS (Jc * Rc * Oc * 4)   // 4,589,568
#define U_ELEMS (Bc * Rc * 4)        //   442,368
#define NROUTES (Jc * Rc)            //   143,424

#define SMEM_BYTES (BT * Rc * 16)    // u_hat fp16-packed uint4: 110592 B

// fp16 copies of the inputs (static device buffers: no allocation)
// W16g layout: per route (j*Rc+r), 4 uint4; uint4 q holds half2 pairs
//   .x=(W[2q][0],W[2q+1][0]) .y=(i=1) .z=(i=2) .w=(i=3)
__device__ uint4  W16g[NROUTES * 4];   // 9.18 MB
__device__ __half u16g[U_ELEMS];       // 0.88 MB

__device__ __forceinline__ unsigned int pk2(float a, float b) {
    __half2 h = __floats2half2_rn(a, b);
    return *reinterpret_cast<unsigned int*>(&h);
}
__device__ __forceinline__ float2 up2(unsigned int v) {
    __half2 h = *reinterpret_cast<__half2*>(&v);
    return __half22float2(h);
}
__device__ __forceinline__ __half2 h2(unsigned int v) {
    return *reinterpret_cast<__half2*>(&v);
}
__device__ __forceinline__ unsigned int u32(__half2 v) {
    return *reinterpret_cast<unsigned int*>(&v);
}
__device__ __forceinline__ unsigned int hadd2u(unsigned int a, unsigned int b) {
    __half2 r = __hadd2(h2(a), h2(b));
    return u32(r);
}

// butterfly-reduce N floats across the warp (all lanes get result)
template<int N>
__device__ __forceinline__ void wredN(float* p) {
#pragma unroll
    for (int s = 16; s; s >>= 1)
#pragma unroll
        for (int q = 0; q < N; q++)
            p[q] += __shfl_xor_sync(0xffffffffu, p[q], s);
}

// ------------------- prep: fp32 -> fp16 (W o-pair-interleaved, u flat) -----
__global__ void __launch_bounds__(256)
prep_kernel(const float* __restrict__ W, const float* __restrict__ u)
{
    const int idx = blockIdx.x * blockDim.x + threadIdx.x;
    if (idx < NROUTES) {
        const float4* f4 = (const float4*)(W + (size_t)idx * 32);
#pragma unroll
        for (int q = 0; q < 4; q++) {
            const float4 lo = f4[2 * q];       // o = 2q,   i = 0..3
            const float4 hi = f4[2 * q + 1];   // o = 2q+1, i = 0..3
            uint4 o;
            o.x = pk2(lo.x, hi.x);
            o.y = pk2(lo.y, hi.y);
            o.z = pk2(lo.z, hi.z);
            o.w = pk2(lo.w, hi.w);
            W16g[(size_t)idx * 4 + q] = o;
        }
    }
    if (idx < U_ELEMS / 8) {
        const float4* p = (const float4*)u + (size_t)idx * 2;
        const float4 a = p[0], b = p[1];
        uint4 o;
        o.x = pk2(a.x, a.y); o.y = pk2(a.z, a.w);
        o.z = pk2(b.x, b.y); o.w = pk2(b.z, b.w);
        ((uint4*)u16g)[idx] = o;
    }
}

// ------------------------------ main kernel ------------------------------
__global__ void __launch_bounds__(TT, 2)
digitcaps_kernel(float* __restrict__ out)
{
    extern __shared__ uint4 uh[];              // [BT][Rc]

    const int g    = blockIdx.x;
    const int j    = blockIdx.y;
    const int b0   = g * BT;
    const int t    = threadIdx.x;
    const int warp = t >> 5;
    const int lane = t & 31;

    const uint4* __restrict__ W4  = W16g + (size_t)j * Rc * 4;
    const uint2* __restrict__ u2p = (const uint2*)u16g;

    // ====== gen: u_hat -> smem, pure HFMA2 (no cvt, no repack) ================
#pragma unroll
    for (int k = 0; k < KR; k++) {
        const int r = t + k * TT;
        uint4 w[4];
#pragma unroll
        for (int q = 0; q < 4; q++) w[q] = W4[(size_t)r * 4 + q];
#pragma unroll
        for (int b = 0; b < BT; b++) {
            const uint2 uu = u2p[(size_t)(b0 + b) * Rc + r];
            const __half2 x01 = h2(uu.x), x23 = h2(uu.y);
            const __half2 b0h = __low2half2(x01),  b1h = __high2half2(x01);
            const __half2 b2h = __low2half2(x23),  b3h = __high2half2(x23);
            uint4 pkv;
            unsigned int* pk = (unsigned int*)&pkv;
#pragma unroll
            for (int q = 0; q < 4; q++) {
                __half2 acc = __hmul2(h2(((const unsigned int*)&w[q])[0]), b0h);
                acc = __hfma2(h2(((const unsigned int*)&w[q])[1]), b1h, acc);
                acc = __hfma2(h2(((const unsigned int*)&w[q])[2]), b2h, acc);
                acc = __hfma2(h2(((const unsigned int*)&w[q])[3]), b3h, acc);
                pk[q] = u32(acc);
            }
            uh[b * Rc + r] = pkv;
        }
    }
    __syncthreads();        // the only barrier

    // ============== routing: warp b owns batch b, fully warp-private ===========
    if (warp < BT) {
        const uint4* __restrict__ base = uh + warp * Rc + lane;

        // ---- pass 0 (half2): s0 = mean_r u_hat ; v0 = squash(s0) ----
        // fp16 accumulation only perturbs softmax weights (harmless).
        unsigned int h0 = 0u, h1 = 0u, h2v = 0u, h3 = 0u;
#pragma unroll 9
        for (int i = 0; i < RW; i++) {
            const uint4 v = base[i * 32];
            h0 = hadd2u(h0, v.x); h1 = hadd2u(h1, v.y);
            h2v = hadd2u(h2v, v.z); h3 = hadd2u(h3, v.w);
        }
#pragma unroll
        for (int s = 16; s; s >>= 1) {
            h0 = hadd2u(h0, __shfl_xor_sync(0xffffffffu, h0, s));
            h1 = hadd2u(h1, __shfl_xor_sync(0xffffffffu, h1, s));
            h2v = hadd2u(h2v, __shfl_xor_sync(0xffffffffu, h2v, s));
            h3 = hadd2u(h3, __shfl_xor_sync(0xffffffffu, h3, s));
        }
        float v0[Oc];
        {
            const float2 f0 = up2(h0), f1 = up2(h1), f2 = up2(h2v), f3 = up2(h3);
            float s[Oc] = { f0.x, f0.y, f1.x, f1.y, f2.x, f2.y, f3.x, f3.y };
            float sq = 0.f;
#pragma unroll
            for (int o = 0; o < Oc; o++) { s[o] *= (1.0f / (float)Rc); sq += s[o] * s[o]; }
            const float scl = sqrtf(sq) / (1.f + sq);
#pragma unroll
            for (int o = 0; o < Oc; o++) v0[o] = s[o] * scl;
        }

        // ---- pass 1: e = exp(<uh,v0>) ; weighted sums -> v1 (scalar fp32) ----
        float p[9];
#pragma unroll
        for (int q = 0; q < 9; q++) p[q] = 0.f;
#pragma unroll 9
        for (int i = 0; i < RW; i++) {
            const uint4 v = base[i * 32];
            const float2 f0 = up2(v.x), f1 = up2(v.y), f2 = up2(v.z), f3 = up2(v.w);
            const float a = f0.x * v0[0] + f0.y * v0[1] + f1.x * v0[2] + f1.y * v0[3]
                          + f2.x * v0[4] + f2.y * v0[5] + f3.x * v0[6] + f3.y * v0[7];
            const float e = __expf(a);
            p[8] += e;
            p[0] += e * f0.x; p[1] += e * f0.y;
            p[2] += e * f1.x; p[3] += e * f1.y;
            p[4] += e * f2.x; p[5] += e * f2.y;
            p[6] += e * f3.x; p[7] += e * f3.y;
        }
        wredN<9>(p);
        float vs[Oc];   // vs = v0 + v1  (b2 = <uh,v0> + <uh,v1> = <uh,vs>)
        {
            const float inv = 1.f / p[8];
            float sq = 0.f;
#pragma unroll
            for (int o = 0; o < Oc; o++) { p[o] *= inv; sq += p[o] * p[o]; }
            const float scl = sqrtf(sq) / (1.f + sq);
#pragma unroll
            for (int o = 0; o < Oc; o++) vs[o] = v0[o] + p[o] * scl;
        }

        // ---- pass 2: e = exp(<uh,vs>) ; weighted sums -> v2 -> out ----
#pragma unroll
        for (int q = 0; q < 9; q++) p[q] = 0.f;
#pragma unroll 9
        for (int i = 0; i < RW; i++) {
            const uint4 v = base[i * 32];
            const float2 f0 = up2(v.x), f1 = up2(v.y), f2 = up2(v.z), f3 = up2(v.w);
            const float a = f0.x * vs[0] + f0.y * vs[1] + f1.x * vs[2] + f1.y * vs[3]
                          + f2.x * vs[4] + f2.y * vs[5] + f3.x * vs[6] + f3.y * vs[7];
            const float e = __expf(a);
            p[8] += e;
            p[0] += e * f0.x; p[1] += e * f0.y;
            p[2] += e * f1.x; p[3] += e * f1.y;
            p[4] += e * f2.x; p[5] += e * f2.y;
            p[6] += e * f3.x; p[7] += e * f3.y;
        }
        wredN<9>(p);
        {
            const float inv = 1.f / p[8];
            float sq = 0.f;
#pragma unroll
            for (int o = 0; o < Oc; o++) { p[o] *= inv; sq += p[o] * p[o]; }
            const float scl = sqrtf(sq) / (1.f + sq);
            if (lane < Oc)
                out[((size_t)(b0 + warp) * Jc + j) * Oc + lane] = p[lane] * scl;
        }
    }
}

extern "C" void kernel_launch(void* const* d_in, const int* in_sizes, int n_in,
                              void* d_out, int out_size)
{
    const float* u = (const float*)d_in[0];
    const float* W = (const float*)d_in[1];
    if (n_in >= 2 && in_sizes[0] > in_sizes[1]) {   // defensive order check
        const float* tmp = u; u = W; W = tmp;
    }

    cudaFuncSetAttribute(digitcaps_kernel,
                         cudaFuncAttributeMaxDynamicSharedMemorySize, SMEM_BYTES);

    // 1) convert W (o-pair-interleaved) and u to fp16 staging buffers
    prep_kernel<<<(NROUTES + 255) / 256, 256>>>(W, u);
    // 2) fused capsule-routing kernel
    dim3 grid(Bc / BT, Jc);   // (16, 166)
    digitcaps_kernel<<<grid, TT, SMEM_BYTES>>>((float*)d_out);
}